// round 1
// baseline (speedup 1.0000x reference)
#include <cuda_runtime.h>
#include <math.h>

#define NMAX 50048

__device__ float g_WT[3][128*256];     // per layer, k-major: [k][c], c<128 -> Wm, c>=128 -> Wu
__device__ float g_m[NMAX*128];
__device__ float g_agg[NMAX*128];
__device__ float g_h[2][NMAX*128];
__device__ int   g_is64;

// ---------- f32x2 helpers ----------
__device__ __forceinline__ unsigned long long dup2(float v) {
    unsigned long long r;
    asm("mov.b64 %0, {%1, %1};" : "=l"(r) : "f"(v));
    return r;
}
__device__ __forceinline__ unsigned long long pk2(float a, float b) {
    unsigned long long r;
    asm("mov.b64 %0, {%1, %2};" : "=l"(r) : "f"(a), "f"(b));
    return r;
}
__device__ __forceinline__ void ffma2(unsigned long long& d, unsigned long long a, unsigned long long b) {
    asm("fma.rn.f32x2 %0, %1, %2, %0;" : "+l"(d) : "l"(a), "l"(b));
}
__device__ __forceinline__ float2 upk(unsigned long long v) {
    float2 f;
    asm("mov.b64 {%0, %1}, %2;" : "=f"(f.x), "=f"(f.y) : "l"(v));
    return f;
}

// ---------- prep: transpose weights to k-major, detect edge_index dtype ----------
__global__ void prep_kernel(const float* __restrict__ Wm0, const float* __restrict__ Wu0,
                            const float* __restrict__ Wm1, const float* __restrict__ Wu1,
                            const float* __restrict__ Wm2, const float* __restrict__ Wu2,
                            const void* __restrict__ ei, int E) {
    int idx = blockIdx.x * blockDim.x + threadIdx.x;
    if (idx == 0) {
        // int64 little-endian with values < 2^31 -> every odd int32 word is 0
        const int* p = (const int*)ei;
        int is64 = 1;
        for (int i = 0; i < 32; i++) {
            if (p[2*i + 1] != 0) { is64 = 0; break; }
        }
        g_is64 = is64;
    }
    const int total = 3 * 128 * 256;
    for (int t = idx; t < total; t += gridDim.x * blockDim.x) {
        int l = t / (128 * 256);
        int r = t % (128 * 256);
        int k = r / 256;
        int c = r % 256;
        const float* W;
        if (c < 128) W = (l == 0) ? Wm0 : (l == 1) ? Wm1 : Wm2;
        else         W = (l == 0) ? Wu0 : (l == 1) ? Wu1 : Wu2;
        int cc = c & 127;
        g_WT[l][k * 256 + c] = W[cc * 128 + k];
    }
}

// ---------- dual GEMM: m = x@Wm.T ; agg = x@Wu.T + bu ----------
// BM=64 rows/tile, 256 threads. smem: xs (x duplicated as f32x2 pairs, 64KB) + Ws (128KB).
#define DUAL_SMEM (64*128*8 + 128*256*4)
__global__ __launch_bounds__(256, 1) void dual_gemm(
    const float* __restrict__ x, const float* __restrict__ WT,
    const float* __restrict__ bu,
    float* __restrict__ outm, float* __restrict__ outagg, int N)
{
    extern __shared__ char sm_[];
    unsigned long long* xs = (unsigned long long*)sm_;     // [64][128] u64 (dup pairs)
    float* Ws = (float*)(sm_ + 64*128*8);                  // [128][256]
    int tid = threadIdx.x;

    #pragma unroll 4
    for (int i = tid; i < 128*256/4; i += 256)
        ((float4*)Ws)[i] = ((const float4*)WT)[i];

    int tx = tid & 31, ty = tid >> 5;
    int r0 = ty * 8;
    int ntiles = (N + 63) >> 6;

    for (int tile = blockIdx.x; tile < ntiles; tile += gridDim.x) {
        int row0 = tile << 6;
        __syncthreads();
        // stage x tile, each float duplicated into both f32x2 halves
        for (int i = tid; i < 64*32; i += 256) {
            int r = i >> 5;
            int c4 = (i & 31) << 2;
            float4 v = make_float4(0.f, 0.f, 0.f, 0.f);
            if (row0 + r < N) v = *(const float4*)(x + (size_t)(row0 + r)*128 + c4);
            unsigned long long* d = xs + r*128 + c4;
            d[0] = dup2(v.x); d[1] = dup2(v.y); d[2] = dup2(v.z); d[3] = dup2(v.w);
        }
        __syncthreads();

        unsigned long long am[8][2], au[8][2];
        #pragma unroll
        for (int i = 0; i < 8; i++) { am[i][0]=0ULL; am[i][1]=0ULL; au[i][0]=0ULL; au[i][1]=0ULL; }

        #pragma unroll 4
        for (int k = 0; k < 128; k++) {
            float4 wm = *(const float4*)(Ws + k*256 + 4*tx);
            float4 wu = *(const float4*)(Ws + k*256 + 128 + 4*tx);
            unsigned long long wm0 = pk2(wm.x, wm.y), wm1 = pk2(wm.z, wm.w);
            unsigned long long wu0 = pk2(wu.x, wu.y), wu1 = pk2(wu.z, wu.w);
            #pragma unroll
            for (int i = 0; i < 8; i++) {
                unsigned long long xv = xs[(r0 + i)*128 + k];
                ffma2(am[i][0], xv, wm0);
                ffma2(am[i][1], xv, wm1);
                ffma2(au[i][0], xv, wu0);
                ffma2(au[i][1], xv, wu1);
            }
        }

        float4 bb = *(const float4*)(bu + 4*tx);
        #pragma unroll
        for (int i = 0; i < 8; i++) {
            int gr = row0 + r0 + i;
            if (gr < N) {
                float2 a0 = upk(am[i][0]), a1 = upk(am[i][1]);
                *(float4*)(outm + (size_t)gr*128 + 4*tx) = make_float4(a0.x, a0.y, a1.x, a1.y);
                float2 b0 = upk(au[i][0]), b1 = upk(au[i][1]);
                *(float4*)(outagg + (size_t)gr*128 + 4*tx) =
                    make_float4(b0.x + bb.x, b0.y + bb.y, b1.x + bb.z, b1.y + bb.w);
            }
        }
    }
}

// ---------- edge scatter: agg[dst] += w * m[src], one warp per edge ----------
__global__ void edge_scatter(const void* __restrict__ eidx, const float* __restrict__ ew,
                             const float* __restrict__ m, float* __restrict__ agg, int E)
{
    int w = (blockIdx.x * blockDim.x + threadIdx.x) >> 5;
    int lane = threadIdx.x & 31;
    if (w >= E) return;
    int src, dst;
    if (g_is64) {
        const long long* p = (const long long*)eidx;
        src = (int)p[w];
        dst = (int)p[E + w];
    } else {
        const int* p = (const int*)eidx;
        src = p[w];
        dst = p[E + w];
    }
    float wt = ew[w];
    float4 v = *(const float4*)(m + (size_t)src*128 + lane*4);
    float* ap = agg + (size_t)dst*128 + lane*4;
    asm volatile("red.global.add.v4.f32 [%0], {%1,%2,%3,%4};"
                 :: "l"(ap), "f"(v.x*wt), "f"(v.y*wt), "f"(v.z*wt), "f"(v.w*wt)
                 : "memory");
}

// ---------- elementwise tanh ----------
__global__ void tanh_kernel(const float* __restrict__ a, float* __restrict__ h, int n4) {
    int i = blockIdx.x * blockDim.x + threadIdx.x;
    if (i < n4) {
        float4 v = ((const float4*)a)[i];
        v.x = tanhf(v.x); v.y = tanhf(v.y); v.z = tanhf(v.z); v.w = tanhf(v.w);
        ((float4*)h)[i] = v;
    }
}

// ---------- output GEMM: out = h @ Wout.T + bout  (C=32) ----------
#define OUT_SMEM (64*128*4 + 32*132*4)
__global__ __launch_bounds__(256, 1) void out_gemm(
    const float* __restrict__ h, const float* __restrict__ Wout,
    const float* __restrict__ bout, float* __restrict__ out, int N)
{
    extern __shared__ char sm_[];
    float* xs = (float*)sm_;                 // [64][128]
    float* Wo = (float*)(sm_ + 64*128*4);    // [32][132] padded

    int tid = threadIdx.x;
    for (int i = tid; i < 32*32; i += 256) {   // 32 rows x 32 float4
        int r = i >> 5;
        int c4 = (i & 31) << 2;
        float4 v = *(const float4*)(Wout + r*128 + c4);
        *(float4*)(Wo + r*132 + c4) = v;
    }
    int tx = tid & 31, ty = tid >> 5;
    int r0 = ty * 8;
    float bo = bout[tx];
    int ntiles = (N + 63) >> 6;

    for (int tile = blockIdx.x; tile < ntiles; tile += gridDim.x) {
        int row0 = tile << 6;
        __syncthreads();
        for (int i = tid; i < 64*32; i += 256) {
            int r = i >> 5;
            int c4 = (i & 31) << 2;
            float4 v = make_float4(0.f, 0.f, 0.f, 0.f);
            if (row0 + r < N) v = *(const float4*)(h + (size_t)(row0 + r)*128 + c4);
            *(float4*)(xs + r*128 + c4) = v;
        }
        __syncthreads();

        float acc[8];
        #pragma unroll
        for (int i = 0; i < 8; i++) acc[i] = 0.f;

        #pragma unroll 4
        for (int k4 = 0; k4 < 128; k4 += 4) {
            float4 wv = *(const float4*)(Wo + tx*132 + k4);
            #pragma unroll
            for (int i = 0; i < 8; i++) {
                float4 xv = *(const float4*)(xs + (r0 + i)*128 + k4);
                acc[i] = fmaf(xv.x, wv.x, acc[i]);
                acc[i] = fmaf(xv.y, wv.y, acc[i]);
                acc[i] = fmaf(xv.z, wv.z, acc[i]);
                acc[i] = fmaf(xv.w, wv.w, acc[i]);
            }
        }
        #pragma unroll
        for (int i = 0; i < 8; i++) {
            int gr = row0 + r0 + i;
            if (gr < N) out[(size_t)gr*32 + tx] = acc[i] + bo;
        }
    }
}

extern "C" void kernel_launch(void* const* d_in, const int* in_sizes, int n_in,
                              void* d_out, int out_size) {
    const float* x    = (const float*)d_in[0];
    const void*  ei   = d_in[1];
    const float* ew   = (const float*)d_in[2];
    const float* Wm0  = (const float*)d_in[3];
    const float* Wu0  = (const float*)d_in[4];
    const float* bu0  = (const float*)d_in[5];
    const float* Wm1  = (const float*)d_in[6];
    const float* Wu1  = (const float*)d_in[7];
    const float* bu1  = (const float*)d_in[8];
    const float* Wm2  = (const float*)d_in[9];
    const float* Wu2  = (const float*)d_in[10];
    const float* bu2  = (const float*)d_in[11];
    const float* Wout = (const float*)d_in[12];
    const float* bout = (const float*)d_in[13];
    float* out = (float*)d_out;

    int N = in_sizes[0] / 128;
    int E = in_sizes[2];

    float *pWT, *pm, *pagg, *ph;
    cudaGetSymbolAddress((void**)&pWT,  g_WT);
    cudaGetSymbolAddress((void**)&pm,   g_m);
    cudaGetSymbolAddress((void**)&pagg, g_agg);
    cudaGetSymbolAddress((void**)&ph,   g_h);

    cudaFuncSetAttribute(dual_gemm, cudaFuncAttributeMaxDynamicSharedMemorySize, DUAL_SMEM);
    cudaFuncSetAttribute(out_gemm,  cudaFuncAttributeMaxDynamicSharedMemorySize, OUT_SMEM);

    prep_kernel<<<96, 256>>>(Wm0, Wu0, Wm1, Wu1, Wm2, Wu2, ei, E);

    int eblocks = (E + 7) / 8;        // 8 warps (edges) per 256-thread block
    int n4 = (N * 128) / 4;

    const float* cur = x;
    for (int l = 0; l < 3; l++) {
        const float* bu = (l == 0) ? bu0 : (l == 1) ? bu1 : bu2;
        dual_gemm<<<148, 256, DUAL_SMEM>>>(cur, pWT + (size_t)l*128*256, bu, pm, pagg, N);
        edge_scatter<<<eblocks, 256>>>(ei, ew, pm, pagg, E);
        float* hbuf = ph + (size_t)(l & 1) * NMAX * 128;
        tanh_kernel<<<(n4 + 255) / 256, 256>>>(pagg, hbuf, n4);
        cur = hbuf;
    }
    out_gemm<<<148, 256, OUT_SMEM>>>(cur, Wout, bout, out, N);
    (void)n_in; (void)out_size;
}

// round 2
// speedup vs baseline: 1.2035x; 1.2035x over previous
#include <cuda_runtime.h>
#include <math.h>

#define NMAX 50048
#define EMAX 1000000

__device__ float g_WT[3][128*256];     // per layer, k-major: [k][c], c<128 -> Wm, c>=128 -> Wu
__device__ float g_m[NMAX*128];
__device__ float g_u[NMAX*128];        // x@Wu.T + bu
__device__ float g_h[2][NMAX*128];
__device__ int   g_is64;
__device__ int   g_cnt[NMAX];
__device__ int   g_off[NMAX + 1];
__device__ int   g_cur[NMAX];
__device__ int   g_src_sorted[EMAX];
__device__ float g_w_sorted[EMAX];

// ---------- f32x2 helpers ----------
__device__ __forceinline__ unsigned long long dup2(float v) {
    unsigned long long r;
    asm("mov.b64 %0, {%1, %1};" : "=l"(r) : "f"(v));
    return r;
}
__device__ __forceinline__ unsigned long long pk2(float a, float b) {
    unsigned long long r;
    asm("mov.b64 %0, {%1, %2};" : "=l"(r) : "f"(a), "f"(b));
    return r;
}
__device__ __forceinline__ void ffma2(unsigned long long& d, unsigned long long a, unsigned long long b) {
    asm("fma.rn.f32x2 %0, %1, %2, %0;" : "+l"(d) : "l"(a), "l"(b));
}
__device__ __forceinline__ float2 upk(unsigned long long v) {
    float2 f;
    asm("mov.b64 {%0, %1}, %2;" : "=f"(f.x), "=f"(f.y) : "l"(v));
    return f;
}

// ---------- prep: transpose weights to k-major, detect edge_index dtype, zero counters ----------
__global__ void prep_kernel(const float* __restrict__ Wm0, const float* __restrict__ Wu0,
                            const float* __restrict__ Wm1, const float* __restrict__ Wu1,
                            const float* __restrict__ Wm2, const float* __restrict__ Wu2,
                            const void* __restrict__ ei, int E, int N) {
    int idx = blockIdx.x * blockDim.x + threadIdx.x;
    if (idx == 0) {
        // int64 little-endian with values < 2^31 -> every odd int32 word is 0
        const int* p = (const int*)ei;
        int is64 = 1;
        for (int i = 0; i < 32; i++) {
            if (p[2*i + 1] != 0) { is64 = 0; break; }
        }
        g_is64 = is64;
    }
    for (int t = idx; t < N; t += gridDim.x * blockDim.x) g_cnt[t] = 0;
    const int total = 3 * 128 * 256;
    for (int t = idx; t < total; t += gridDim.x * blockDim.x) {
        int l = t / (128 * 256);
        int r = t % (128 * 256);
        int k = r / 256;
        int c = r % 256;
        const float* W;
        if (c < 128) W = (l == 0) ? Wm0 : (l == 1) ? Wm1 : Wm2;
        else         W = (l == 0) ? Wu0 : (l == 1) ? Wu1 : Wu2;
        int cc = c & 127;
        g_WT[l][k * 256 + c] = W[cc * 128 + k];
    }
}

// ---------- CSR build ----------
__global__ void hist_kernel(const void* __restrict__ ei, int E) {
    int i = blockIdx.x * blockDim.x + threadIdx.x;
    if (i >= E) return;
    int dst = g_is64 ? (int)((const long long*)ei)[E + i] : ((const int*)ei)[E + i];
    atomicAdd(&g_cnt[dst], 1);
}

__global__ __launch_bounds__(1024) void scan_kernel(int N) {
    __shared__ int part[1024];
    int t = threadIdx.x;
    int chunk = (N + 1023) / 1024;
    int b = t * chunk;
    int e = min(b + chunk, N);
    int s = 0;
    for (int i = b; i < e; i++) s += g_cnt[i];
    part[t] = s;
    __syncthreads();
    // inclusive Hillis-Steele
    for (int d = 1; d < 1024; d <<= 1) {
        int v = (t >= d) ? part[t - d] : 0;
        __syncthreads();
        part[t] += v;
        __syncthreads();
    }
    int run = (t == 0) ? 0 : part[t - 1];
    for (int i = b; i < e; i++) {
        int c = g_cnt[i];
        g_off[i] = run;
        g_cur[i] = run;
        run += c;
    }
    if (e == N && b <= N) g_off[N] = run;
}

__global__ void scatter_kernel(const void* __restrict__ ei, const float* __restrict__ ew, int E) {
    int i = blockIdx.x * blockDim.x + threadIdx.x;
    if (i >= E) return;
    int src, dst;
    if (g_is64) {
        const long long* p = (const long long*)ei;
        src = (int)p[i];
        dst = (int)p[E + i];
    } else {
        const int* p = (const int*)ei;
        src = p[i];
        dst = p[E + i];
    }
    int pos = atomicAdd(&g_cur[dst], 1);
    g_src_sorted[pos] = src;
    g_w_sorted[pos]   = ew[i];
}

// ---------- dual GEMM: m = x@Wm.T ; u = x@Wu.T + bu ----------
#define DUAL_SMEM (64*128*8 + 128*256*4)
__global__ __launch_bounds__(256, 1) void dual_gemm(
    const float* __restrict__ x, const float* __restrict__ WT,
    const float* __restrict__ bu,
    float* __restrict__ outm, float* __restrict__ outu, int N)
{
    extern __shared__ char sm_[];
    unsigned long long* xs = (unsigned long long*)sm_;     // [64][128] u64 (dup pairs)
    float* Ws = (float*)(sm_ + 64*128*8);                  // [128][256]
    int tid = threadIdx.x;

    #pragma unroll 4
    for (int i = tid; i < 128*256/4; i += 256)
        ((float4*)Ws)[i] = ((const float4*)WT)[i];

    int tx = tid & 31, ty = tid >> 5;
    int r0 = ty * 8;
    int ntiles = (N + 63) >> 6;

    for (int tile = blockIdx.x; tile < ntiles; tile += gridDim.x) {
        int row0 = tile << 6;
        __syncthreads();
        for (int i = tid; i < 64*32; i += 256) {
            int r = i >> 5;
            int c4 = (i & 31) << 2;
            float4 v = make_float4(0.f, 0.f, 0.f, 0.f);
            if (row0 + r < N) v = *(const float4*)(x + (size_t)(row0 + r)*128 + c4);
            unsigned long long* d = xs + r*128 + c4;
            d[0] = dup2(v.x); d[1] = dup2(v.y); d[2] = dup2(v.z); d[3] = dup2(v.w);
        }
        __syncthreads();

        unsigned long long am[8][2], au[8][2];
        #pragma unroll
        for (int i = 0; i < 8; i++) { am[i][0]=0ULL; am[i][1]=0ULL; au[i][0]=0ULL; au[i][1]=0ULL; }

        #pragma unroll 4
        for (int k = 0; k < 128; k++) {
            float4 wm = *(const float4*)(Ws + k*256 + 4*tx);
            float4 wu = *(const float4*)(Ws + k*256 + 128 + 4*tx);
            unsigned long long wm0 = pk2(wm.x, wm.y), wm1 = pk2(wm.z, wm.w);
            unsigned long long wu0 = pk2(wu.x, wu.y), wu1 = pk2(wu.z, wu.w);
            #pragma unroll
            for (int i = 0; i < 8; i++) {
                unsigned long long xv = xs[(r0 + i)*128 + k];
                ffma2(am[i][0], xv, wm0);
                ffma2(am[i][1], xv, wm1);
                ffma2(au[i][0], xv, wu0);
                ffma2(au[i][1], xv, wu1);
            }
        }

        float4 bb = *(const float4*)(bu + 4*tx);
        #pragma unroll
        for (int i = 0; i < 8; i++) {
            int gr = row0 + r0 + i;
            if (gr < N) {
                float2 a0 = upk(am[i][0]), a1 = upk(am[i][1]);
                *(float4*)(outm + (size_t)gr*128 + 4*tx) = make_float4(a0.x, a0.y, a1.x, a1.y);
                float2 b0 = upk(au[i][0]), b1 = upk(au[i][1]);
                *(float4*)(outu + (size_t)gr*128 + 4*tx) =
                    make_float4(b0.x + bb.x, b0.y + bb.y, b1.x + bb.z, b1.y + bb.w);
            }
        }
    }
}

// ---------- fused CSR aggregate + tanh: h[d] = tanh(u[d] + sum_e w_e * m[src_e]) ----------
__global__ __launch_bounds__(256) void agg_tanh(
    const float* __restrict__ m, const float* __restrict__ u,
    float* __restrict__ h, int N)
{
    int node = (blockIdx.x * blockDim.x + threadIdx.x) >> 5;
    int lane = threadIdx.x & 31;
    if (node >= N) return;
    int b = g_off[node], e = g_off[node + 1];

    float4 acc = *(const float4*)(u + (size_t)node*128 + lane*4);

    int i = b;
    for (; i + 4 <= e; i += 4) {
        int   s0 = g_src_sorted[i],   s1 = g_src_sorted[i+1];
        int   s2 = g_src_sorted[i+2], s3 = g_src_sorted[i+3];
        float w0 = g_w_sorted[i],     w1 = g_w_sorted[i+1];
        float w2 = g_w_sorted[i+2],   w3 = g_w_sorted[i+3];
        float4 v0 = *(const float4*)(m + (size_t)s0*128 + lane*4);
        float4 v1 = *(const float4*)(m + (size_t)s1*128 + lane*4);
        float4 v2 = *(const float4*)(m + (size_t)s2*128 + lane*4);
        float4 v3 = *(const float4*)(m + (size_t)s3*128 + lane*4);
        acc.x = fmaf(w0, v0.x, fmaf(w1, v1.x, fmaf(w2, v2.x, fmaf(w3, v3.x, acc.x))));
        acc.y = fmaf(w0, v0.y, fmaf(w1, v1.y, fmaf(w2, v2.y, fmaf(w3, v3.y, acc.y))));
        acc.z = fmaf(w0, v0.z, fmaf(w1, v1.z, fmaf(w2, v2.z, fmaf(w3, v3.z, acc.z))));
        acc.w = fmaf(w0, v0.w, fmaf(w1, v1.w, fmaf(w2, v2.w, fmaf(w3, v3.w, acc.w))));
    }
    for (; i < e; i++) {
        int   s = g_src_sorted[i];
        float w = g_w_sorted[i];
        float4 v = *(const float4*)(m + (size_t)s*128 + lane*4);
        acc.x = fmaf(w, v.x, acc.x);
        acc.y = fmaf(w, v.y, acc.y);
        acc.z = fmaf(w, v.z, acc.z);
        acc.w = fmaf(w, v.w, acc.w);
    }
    acc.x = tanhf(acc.x); acc.y = tanhf(acc.y);
    acc.z = tanhf(acc.z); acc.w = tanhf(acc.w);
    *(float4*)(h + (size_t)node*128 + lane*4) = acc;
}

// ---------- output GEMM: out = h @ Wout.T + bout  (C=32) ----------
#define OUT_SMEM (64*128*4 + 32*132*4)
__global__ __launch_bounds__(256, 1) void out_gemm(
    const float* __restrict__ h, const float* __restrict__ Wout,
    const float* __restrict__ bout, float* __restrict__ out, int N)
{
    extern __shared__ char sm_[];
    float* xs = (float*)sm_;                 // [64][128]
    float* Wo = (float*)(sm_ + 64*128*4);    // [32][132] padded

    int tid = threadIdx.x;
    for (int i = tid; i < 32*32; i += 256) {
        int r = i >> 5;
        int c4 = (i & 31) << 2;
        float4 v = *(const float4*)(Wout + r*128 + c4);
        *(float4*)(Wo + r*132 + c4) = v;
    }
    int tx = tid & 31, ty = tid >> 5;
    int r0 = ty * 8;
    float bo = bout[tx];
    int ntiles = (N + 63) >> 6;

    for (int tile = blockIdx.x; tile < ntiles; tile += gridDim.x) {
        int row0 = tile << 6;
        __syncthreads();
        for (int i = tid; i < 64*32; i += 256) {
            int r = i >> 5;
            int c4 = (i & 31) << 2;
            float4 v = make_float4(0.f, 0.f, 0.f, 0.f);
            if (row0 + r < N) v = *(const float4*)(h + (size_t)(row0 + r)*128 + c4);
            *(float4*)(xs + r*128 + c4) = v;
        }
        __syncthreads();

        float acc[8];
        #pragma unroll
        for (int i = 0; i < 8; i++) acc[i] = 0.f;

        #pragma unroll 4
        for (int k4 = 0; k4 < 128; k4 += 4) {
            float4 wv = *(const float4*)(Wo + tx*132 + k4);
            #pragma unroll
            for (int i = 0; i < 8; i++) {
                float4 xv = *(const float4*)(xs + (r0 + i)*128 + k4);
                acc[i] = fmaf(xv.x, wv.x, acc[i]);
                acc[i] = fmaf(xv.y, wv.y, acc[i]);
                acc[i] = fmaf(xv.z, wv.z, acc[i]);
                acc[i] = fmaf(xv.w, wv.w, acc[i]);
            }
        }
        #pragma unroll
        for (int i = 0; i < 8; i++) {
            int gr = row0 + r0 + i;
            if (gr < N) out[(size_t)gr*32 + tx] = acc[i] + bo;
        }
    }
}

extern "C" void kernel_launch(void* const* d_in, const int* in_sizes, int n_in,
                              void* d_out, int out_size) {
    const float* x    = (const float*)d_in[0];
    const void*  ei   = d_in[1];
    const float* ew   = (const float*)d_in[2];
    const float* Wm0  = (const float*)d_in[3];
    const float* Wu0  = (const float*)d_in[4];
    const float* bu0  = (const float*)d_in[5];
    const float* Wm1  = (const float*)d_in[6];
    const float* Wu1  = (const float*)d_in[7];
    const float* bu1  = (const float*)d_in[8];
    const float* Wm2  = (const float*)d_in[9];
    const float* Wu2  = (const float*)d_in[10];
    const float* bu2  = (const float*)d_in[11];
    const float* Wout = (const float*)d_in[12];
    const float* bout = (const float*)d_in[13];
    float* out = (float*)d_out;

    int N = in_sizes[0] / 128;
    int E = in_sizes[2];

    float *pWT, *pm, *pu, *ph;
    cudaGetSymbolAddress((void**)&pWT, g_WT);
    cudaGetSymbolAddress((void**)&pm,  g_m);
    cudaGetSymbolAddress((void**)&pu,  g_u);
    cudaGetSymbolAddress((void**)&ph,  g_h);

    cudaFuncSetAttribute(dual_gemm, cudaFuncAttributeMaxDynamicSharedMemorySize, DUAL_SMEM);
    cudaFuncSetAttribute(out_gemm,  cudaFuncAttributeMaxDynamicSharedMemorySize, OUT_SMEM);

    prep_kernel<<<148, 256>>>(Wm0, Wu0, Wm1, Wu1, Wm2, Wu2, ei, E, N);

    int eb = (E + 255) / 256;
    hist_kernel<<<eb, 256>>>(ei, E);
    scan_kernel<<<1, 1024>>>(N);
    scatter_kernel<<<eb, 256>>>(ei, ew, E);

    int ab = (N * 32 + 255) / 256;

    const float* cur = x;
    for (int l = 0; l < 3; l++) {
        const float* bu = (l == 0) ? bu0 : (l == 1) ? bu1 : bu2;
        dual_gemm<<<148, 256, DUAL_SMEM>>>(cur, pWT + (size_t)l*128*256, bu, pm, pu, N);
        float* hbuf = ph + (size_t)(l & 1) * NMAX * 128;
        agg_tanh<<<ab, 256>>>(pm, pu, hbuf, N);
        cur = hbuf;
    }
    out_gemm<<<148, 256, OUT_SMEM>>>(cur, Wout, bout, out, N);
    (void)n_in; (void)out_size;
}

// round 5
// speedup vs baseline: 1.5758x; 1.3093x over previous
#include <cuda_runtime.h>
#include <cuda_bf16.h>
#include <mma.h>
#include <stdint.h>
#include <math.h>

using namespace nvcuda;

#define NMAX 50048   // 391 * 128, so WMMA tile stores never go OOB
#define EMAX 1000000

__device__ __nv_bfloat16 g_Wbf[3][2][256*128]; // [layer][hi/lo][c][k] row-major
__device__ float g_m[NMAX*128];
__device__ float g_u[NMAX*128];
__device__ float g_h[2][NMAX*128];
__device__ int   g_is64;
__device__ int   g_cnt[NMAX];
__device__ int   g_off[NMAX + 1];
__device__ int   g_cur[NMAX];
__device__ int   g_src_sorted[EMAX];
__device__ float g_w_sorted[EMAX];

// ================= prep: weights -> bf16 hi/lo; dtype detect; cnt zero =================
__global__ void prep_kernel(const float* __restrict__ Wm0, const float* __restrict__ Wu0,
                            const float* __restrict__ Wm1, const float* __restrict__ Wu1,
                            const float* __restrict__ Wm2, const float* __restrict__ Wu2,
                            const void* __restrict__ ei, int E, int N) {
    int idx = blockIdx.x * blockDim.x + threadIdx.x;
    if (idx == 0) {
        const int* p = (const int*)ei;
        int is64 = 1;
        for (int i = 0; i < 32; i++) if (p[2*i + 1] != 0) { is64 = 0; break; }
        g_is64 = is64;
    }
    for (int t = idx; t < N; t += gridDim.x * blockDim.x) g_cnt[t] = 0;

    const int total = 3 * 256 * 128;
    for (int t = idx; t < total; t += gridDim.x * blockDim.x) {
        int l = t / (256 * 128);
        int r = t % (256 * 128);
        int c = r / 128;        // 0..255: Wm rows then Wu rows
        int k = r % 128;
        const float* W;
        if (c < 128) W = (l == 0) ? Wm0 : (l == 1) ? Wm1 : Wm2;
        else         W = (l == 0) ? Wu0 : (l == 1) ? Wu1 : Wu2;
        float v = W[(c & 127) * 128 + k];
        __nv_bfloat16 hi = __float2bfloat16(v);
        __nv_bfloat16 lo = __float2bfloat16(v - __bfloat162float(hi));
        g_Wbf[l][0][c * 128 + k] = hi;
        g_Wbf[l][1][c * 128 + k] = lo;
    }
}

// ================= CSR build =================
__global__ void hist_kernel(const void* __restrict__ ei, int E) {
    int i = blockIdx.x * blockDim.x + threadIdx.x;
    if (i >= E) return;
    int dst = g_is64 ? (int)((const long long*)ei)[E + i] : ((const int*)ei)[E + i];
    atomicAdd(&g_cnt[dst], 1);
}

__global__ __launch_bounds__(1024) void scan_kernel(int N) {
    __shared__ int part[1024];
    int t = threadIdx.x;
    int chunk = (N + 1023) / 1024;
    int b = t * chunk;
    int e = min(b + chunk, N);
    int s = 0;
    for (int i = b; i < e; i++) s += g_cnt[i];
    part[t] = s;
    __syncthreads();
    for (int d = 1; d < 1024; d <<= 1) {
        int v = (t >= d) ? part[t - d] : 0;
        __syncthreads();
        part[t] += v;
        __syncthreads();
    }
    int run = (t == 0) ? 0 : part[t - 1];
    for (int i = b; i < e; i++) {
        int c = g_cnt[i];
        g_off[i] = run;
        g_cur[i] = run;
        run += c;
    }
    if (e == N && b <= N) g_off[N] = run;
}

__global__ void scatter_kernel(const void* __restrict__ ei, const float* __restrict__ ew, int E) {
    int i = blockIdx.x * blockDim.x + threadIdx.x;
    if (i >= E) return;
    int src, dst;
    if (g_is64) {
        const long long* p = (const long long*)ei;
        src = (int)p[i]; dst = (int)p[E + i];
    } else {
        const int* p = (const int*)ei;
        src = p[i]; dst = p[E + i];
    }
    int pos = atomicAdd(&g_cur[dst], 1);
    g_src_sorted[pos] = src;
    g_w_sorted[pos]   = ew[i];
}

// ================= WMMA dual GEMM: m = x@Wm.T ; u = x@Wu.T =================
// 2-way bf16 split: hi*hi + hi*lo + lo*hi accumulated in fp32 fragments.
// smem: xsH/xsL [128][136] bf16, wsH/wsL [256][136] bf16 (B col-major, ldb=136)
#define LDP 136
#define XS_H 0
#define XS_L (128*LDP*2)
#define WS_H (2*128*LDP*2)
#define WS_L (WS_H + 256*LDP*2)
#define GEMM_SMEM (WS_L + 256*LDP*2)

__global__ __launch_bounds__(256, 1) void dual_gemm_wmma(
    const float* __restrict__ x,
    const __nv_bfloat16* __restrict__ Whi, const __nv_bfloat16* __restrict__ Wlo,
    float* __restrict__ outm, float* __restrict__ outu, int N)
{
    extern __shared__ char sm[];
    __nv_bfloat16* xsH = (__nv_bfloat16*)(sm + XS_H);
    __nv_bfloat16* xsL = (__nv_bfloat16*)(sm + XS_L);
    __nv_bfloat16* wsH = (__nv_bfloat16*)(sm + WS_H);
    __nv_bfloat16* wsL = (__nv_bfloat16*)(sm + WS_L);
    int tid = threadIdx.x, warp = tid >> 5;

    // stage weights: 256 rows (cols of B), each 128 bf16 = 16 uint4
    for (int i = tid; i < 256 * 16; i += 256) {
        int r = i >> 4, ch = i & 15;
        ((uint4*)(wsH + r * LDP))[ch] = ((const uint4*)(Whi + r * 128))[ch];
        ((uint4*)(wsL + r * LDP))[ch] = ((const uint4*)(Wlo + r * 128))[ch];
    }

    int ntiles = (N + 127) >> 7;

    for (int tile = blockIdx.x; tile < ntiles; tile += gridDim.x) {
        int row0 = tile << 7;
        __syncthreads();
        // stage x tile -> bf16 hi/lo, 8 floats per chunk
        for (int ch = tid; ch < 2048; ch += 256) {
            int r  = ch >> 4;
            int c0 = (ch & 15) << 3;
            float v[8];
            int gr = row0 + r;
            if (gr < N) {
                float4 a = *(const float4*)(x + (size_t)gr * 128 + c0);
                float4 b = *(const float4*)(x + (size_t)gr * 128 + c0 + 4);
                v[0]=a.x; v[1]=a.y; v[2]=a.z; v[3]=a.w; v[4]=b.x; v[5]=b.y; v[6]=b.z; v[7]=b.w;
            } else {
                #pragma unroll
                for (int j = 0; j < 8; j++) v[j] = 0.f;
            }
            union { unsigned short u[8]; uint4 q; } H, L;
            #pragma unroll
            for (int j = 0; j < 8; j++) {
                __nv_bfloat16 hv = __float2bfloat16(v[j]);
                __nv_bfloat16 lv = __float2bfloat16(v[j] - __bfloat162float(hv));
                H.u[j] = __bfloat16_as_ushort(hv);
                L.u[j] = __bfloat16_as_ushort(lv);
            }
            *(uint4*)(xsH + r * LDP + c0) = H.q;
            *(uint4*)(xsL + r * LDP + c0) = L.q;
        }
        __syncthreads();

        const __nv_bfloat16* xrow = (const __nv_bfloat16*)0;
        // each warp: 16 rows (warp*16), loop 4 N-chunks of 64
        #pragma unroll
        for (int nc = 0; nc < 4; nc++) {
            wmma::fragment<wmma::accumulator, 16, 16, 16, float> acc[4];
            #pragma unroll
            for (int f = 0; f < 4; f++) wmma::fill_fragment(acc[f], 0.0f);

            #pragma unroll
            for (int pass = 0; pass < 3; pass++) {
                const __nv_bfloat16* A = (pass == 2) ? xsL : xsH;
                const __nv_bfloat16* B = (pass == 1) ? wsL : wsH;
                #pragma unroll
                for (int k = 0; k < 8; k++) {
                    wmma::fragment<wmma::matrix_a, 16, 16, 16, __nv_bfloat16, wmma::row_major> af;
                    wmma::load_matrix_sync(af, A + (warp * 16) * LDP + k * 16, LDP);
                    #pragma unroll
                    for (int f = 0; f < 4; f++) {
                        wmma::fragment<wmma::matrix_b, 16, 16, 16, __nv_bfloat16, wmma::col_major> bf;
                        wmma::load_matrix_sync(bf, B + (nc * 64 + f * 16) * LDP + k * 16, LDP);
                        wmma::mma_sync(acc[f], af, bf, acc[f]);
                    }
                }
            }
            int gr0 = row0 + warp * 16;   // always < NMAX (padded buffers)
            #pragma unroll
            for (int f = 0; f < 4; f++) {
                int n0 = nc * 64 + f * 16;
                float* dst = (n0 < 128) ? (outm + (size_t)gr0 * 128 + n0)
                                        : (outu + (size_t)gr0 * 128 + (n0 - 128));
                wmma::store_matrix_sync(dst, acc[f], 128, wmma::mem_row_major);
            }
        }
        (void)xrow;
    }
}

// ================= fused CSR aggregate + bias + tanh =================
__global__ __launch_bounds__(256) void agg_tanh(
    const float* __restrict__ m, const float* __restrict__ u,
    const float* __restrict__ bu, float* __restrict__ h, int N)
{
    int node = (blockIdx.x * blockDim.x + threadIdx.x) >> 5;
    int lane = threadIdx.x & 31;
    if (node >= N) return;
    int b = g_off[node], e = g_off[node + 1];

    float4 bb = *(const float4*)(bu + lane*4);
    float4 uu = *(const float4*)(u + (size_t)node*128 + lane*4);
    float4 acc = make_float4(uu.x + bb.x, uu.y + bb.y, uu.z + bb.z, uu.w + bb.w);

    int i = b;
    for (; i + 4 <= e; i += 4) {
        int   s0 = g_src_sorted[i],   s1 = g_src_sorted[i+1];
        int   s2 = g_src_sorted[i+2], s3 = g_src_sorted[i+3];
        float w0 = g_w_sorted[i],     w1 = g_w_sorted[i+1];
        float w2 = g_w_sorted[i+2],   w3 = g_w_sorted[i+3];
        float4 v0 = *(const float4*)(m + (size_t)s0*128 + lane*4);
        float4 v1 = *(const float4*)(m + (size_t)s1*128 + lane*4);
        float4 v2 = *(const float4*)(m + (size_t)s2*128 + lane*4);
        float4 v3 = *(const float4*)(m + (size_t)s3*128 + lane*4);
        acc.x = fmaf(w0, v0.x, fmaf(w1, v1.x, fmaf(w2, v2.x, fmaf(w3, v3.x, acc.x))));
        acc.y = fmaf(w0, v0.y, fmaf(w1, v1.y, fmaf(w2, v2.y, fmaf(w3, v3.y, acc.y))));
        acc.z = fmaf(w0, v0.z, fmaf(w1, v1.z, fmaf(w2, v2.z, fmaf(w3, v3.z, acc.z))));
        acc.w = fmaf(w0, v0.w, fmaf(w1, v1.w, fmaf(w2, v2.w, fmaf(w3, v3.w, acc.w))));
    }
    for (; i < e; i++) {
        int   s = g_src_sorted[i];
        float w = g_w_sorted[i];
        float4 v = *(const float4*)(m + (size_t)s*128 + lane*4);
        acc.x = fmaf(w, v.x, acc.x);
        acc.y = fmaf(w, v.y, acc.y);
        acc.z = fmaf(w, v.z, acc.z);
        acc.w = fmaf(w, v.w, acc.w);
    }
    acc.x = tanhf(acc.x); acc.y = tanhf(acc.y);
    acc.z = tanhf(acc.z); acc.w = tanhf(acc.w);
    *(float4*)(h + (size_t)node*128 + lane*4) = acc;
}

// ================= output GEMM (C=32) =================
#define OUT_SMEM (64*128*4 + 32*132*4)
__global__ __launch_bounds__(256, 1) void out_gemm(
    const float* __restrict__ h, const float* __restrict__ Wout,
    const float* __restrict__ bout, float* __restrict__ out, int N)
{
    extern __shared__ char sm_[];
    float* xs = (float*)sm_;
    float* Wo = (float*)(sm_ + 64*128*4);

    int tid = threadIdx.x;
    for (int i = tid; i < 32*32; i += 256) {
        int r = i >> 5;
        int c4 = (i & 31) << 2;
        float4 v = *(const float4*)(Wout + r*128 + c4);
        *(float4*)(Wo + r*132 + c4) = v;
    }
    int tx = tid & 31, ty = tid >> 5;
    int r0 = ty * 8;
    float bo = bout[tx];
    int ntiles = (N + 63) >> 6;

    for (int tile = blockIdx.x; tile < ntiles; tile += gridDim.x) {
        int row0 = tile << 6;
        __syncthreads();
        for (int i = tid; i < 64*32; i += 256) {
            int r = i >> 5;
            int c4 = (i & 31) << 2;
            float4 v = make_float4(0.f, 0.f, 0.f, 0.f);
            if (row0 + r < N) v = *(const float4*)(h + (size_t)(row0 + r)*128 + c4);
            *(float4*)(xs + r*128 + c4) = v;
        }
        __syncthreads();

        float acc[8];
        #pragma unroll
        for (int i = 0; i < 8; i++) acc[i] = 0.f;

        #pragma unroll 4
        for (int k4 = 0; k4 < 128; k4 += 4) {
            float4 wv = *(const float4*)(Wo + tx*132 + k4);
            #pragma unroll
            for (int i = 0; i < 8; i++) {
                float4 xv = *(const float4*)(xs + (r0 + i)*128 + k4);
                acc[i] = fmaf(xv.x, wv.x, acc[i]);
                acc[i] = fmaf(xv.y, wv.y, acc[i]);
                acc[i] = fmaf(xv.z, wv.z, acc[i]);
                acc[i] = fmaf(xv.w, wv.w, acc[i]);
            }
        }
        #pragma unroll
        for (int i = 0; i < 8; i++) {
            int gr = row0 + r0 + i;
            if (gr < N) out[(size_t)gr*32 + tx] = acc[i] + bo;
        }
    }
}

extern "C" void kernel_launch(void* const* d_in, const int* in_sizes, int n_in,
                              void* d_out, int out_size) {
    const float* x    = (const float*)d_in[0];
    const void*  ei   = d_in[1];
    const float* ew   = (const float*)d_in[2];
    const float* Wm0  = (const float*)d_in[3];
    const float* Wu0  = (const float*)d_in[4];
    const float* bu0  = (const float*)d_in[5];
    const float* Wm1  = (const float*)d_in[6];
    const float* Wu1  = (const float*)d_in[7];
    const float* bu1  = (const float*)d_in[8];
    const float* Wm2  = (const float*)d_in[9];
    const float* Wu2  = (const float*)d_in[10];
    const float* bu2  = (const float*)d_in[11];
    const float* Wout = (const float*)d_in[12];
    const float* bout = (const float*)d_in[13];
    float* out = (float*)d_out;

    int N = in_sizes[0] / 128;
    int E = in_sizes[2];

    __nv_bfloat16* pW;
    float *pm, *pu, *ph;
    cudaGetSymbolAddress((void**)&pW, g_Wbf);
    cudaGetSymbolAddress((void**)&pm, g_m);
    cudaGetSymbolAddress((void**)&pu, g_u);
    cudaGetSymbolAddress((void**)&ph, g_h);

    cudaFuncSetAttribute(dual_gemm_wmma, cudaFuncAttributeMaxDynamicSharedMemorySize, GEMM_SMEM);
    cudaFuncSetAttribute(out_gemm,       cudaFuncAttributeMaxDynamicSharedMemorySize, OUT_SMEM);

    prep_kernel<<<148, 256>>>(Wm0, Wu0, Wm1, Wu1, Wm2, Wu2, ei, E, N);

    int eb = (E + 255) / 256;
    hist_kernel<<<eb, 256>>>(ei, E);
    scan_kernel<<<1, 1024>>>(N);
    scatter_kernel<<<eb, 256>>>(ei, ew, E);

    int ab = (N * 32 + 255) / 256;

    const float* cur = x;
    for (int l = 0; l < 3; l++) {
        const float* bu = (l == 0) ? bu0 : (l == 1) ? bu1 : bu2;
        const __nv_bfloat16* Whi = pW + (size_t)l * 2 * 256 * 128;
        const __nv_bfloat16* Wlo = Whi + 256 * 128;
        dual_gemm_wmma<<<148, 256, GEMM_SMEM>>>(cur, Whi, Wlo, pm, pu, N);
        float* hbuf = ph + (size_t)(l & 1) * NMAX * 128;
        agg_tanh<<<ab, 256>>>(pm, pu, bu, hbuf, N);
        cur = hbuf;
    }
    out_gemm<<<148, 256, OUT_SMEM>>>(cur, Wout, bout, out, N);
    (void)n_in; (void)out_size;
}

// round 6
// speedup vs baseline: 1.8761x; 1.1906x over previous
#include <cuda_runtime.h>
#include <cuda_bf16.h>
#include <mma.h>
#include <stdint.h>
#include <math.h>

using namespace nvcuda;

#define NMAX 50048   // 391 * 128, so WMMA tile stores never go OOB
#define EMAX 1000000

__device__ __nv_bfloat16 g_Wbf[3][2][256*128]; // [layer][hi/lo][c][k] row-major
__device__ float g_m[NMAX*128];
__device__ float g_u[NMAX*128];
__device__ float g_h[2][NMAX*128];
__device__ int   g_is64;
__device__ int   g_cnt[NMAX];
__device__ int   g_off[NMAX + 1];
__device__ int   g_cur[NMAX];
__device__ int   g_src_sorted[EMAX];
__device__ float g_w_sorted[EMAX];

// ================= prep: weights -> bf16 hi/lo =================
__global__ void prep_kernel(const float* __restrict__ Wm0, const float* __restrict__ Wu0,
                            const float* __restrict__ Wm1, const float* __restrict__ Wu1,
                            const float* __restrict__ Wm2, const float* __restrict__ Wu2) {
    int idx = blockIdx.x * blockDim.x + threadIdx.x;
    const int total = 3 * 256 * 128;
    for (int t = idx; t < total; t += gridDim.x * blockDim.x) {
        int l = t / (256 * 128);
        int r = t % (256 * 128);
        int c = r / 128;        // 0..255: Wm rows then Wu rows
        int k = r % 128;
        const float* W;
        if (c < 128) W = (l == 0) ? Wm0 : (l == 1) ? Wm1 : Wm2;
        else         W = (l == 0) ? Wu0 : (l == 1) ? Wu1 : Wu2;
        float v = W[(c & 127) * 128 + k];
        __nv_bfloat16 hi = __float2bfloat16(v);
        __nv_bfloat16 lo = __float2bfloat16(v - __bfloat162float(hi));
        g_Wbf[l][0][c * 128 + k] = hi;
        g_Wbf[l][1][c * 128 + k] = lo;
    }
}

// ================= CSR build (forked stream) =================
__global__ void zero_kernel(const void* __restrict__ ei, int N) {
    int idx = blockIdx.x * blockDim.x + threadIdx.x;
    if (idx == 0) {
        const int* p = (const int*)ei;
        int is64 = 1;
        for (int i = 0; i < 32; i++) if (p[2*i + 1] != 0) { is64 = 0; break; }
        g_is64 = is64;
    }
    for (int t = idx; t < N; t += gridDim.x * blockDim.x) g_cnt[t] = 0;
}

__global__ void hist_kernel(const void* __restrict__ ei, int E) {
    int i = blockIdx.x * blockDim.x + threadIdx.x;
    if (i >= E) return;
    int dst = g_is64 ? (int)((const long long*)ei)[E + i] : ((const int*)ei)[E + i];
    atomicAdd(&g_cnt[dst], 1);
}

__global__ __launch_bounds__(1024) void scan_kernel(int N) {
    __shared__ int part[1024];
    int t = threadIdx.x;
    int chunk = (N + 1023) / 1024;
    int b = t * chunk;
    int e = min(b + chunk, N);
    int s = 0;
    for (int i = b; i < e; i++) s += g_cnt[i];
    part[t] = s;
    __syncthreads();
    for (int d = 1; d < 1024; d <<= 1) {
        int v = (t >= d) ? part[t - d] : 0;
        __syncthreads();
        part[t] += v;
        __syncthreads();
    }
    int run = (t == 0) ? 0 : part[t - 1];
    for (int i = b; i < e; i++) {
        int c = g_cnt[i];
        g_off[i] = run;
        g_cur[i] = run;
        run += c;
    }
    if (e == N && b <= N) g_off[N] = run;
}

__global__ void scatter_kernel(const void* __restrict__ ei, const float* __restrict__ ew, int E) {
    int i = blockIdx.x * blockDim.x + threadIdx.x;
    if (i >= E) return;
    int src, dst;
    if (g_is64) {
        const long long* p = (const long long*)ei;
        src = (int)p[i]; dst = (int)p[E + i];
    } else {
        const int* p = (const int*)ei;
        src = p[i]; dst = p[E + i];
    }
    int pos = atomicAdd(&g_cur[dst], 1);
    g_src_sorted[pos] = src;
    g_w_sorted[pos]   = ew[i];
}

// ================= WMMA dual GEMM: m = x@Wm.T ; u = x@Wu.T =================
#define LDP 136
#define XS_H 0
#define XS_L (128*LDP*2)
#define WS_H (2*128*LDP*2)
#define WS_L (WS_H + 256*LDP*2)
#define GEMM_SMEM (WS_L + 256*LDP*2)

__global__ __launch_bounds__(256, 1) void dual_gemm_wmma(
    const float* __restrict__ x,
    const __nv_bfloat16* __restrict__ Whi, const __nv_bfloat16* __restrict__ Wlo,
    float* __restrict__ outm, float* __restrict__ outu, int N)
{
    extern __shared__ char sm[];
    __nv_bfloat16* xsH = (__nv_bfloat16*)(sm + XS_H);
    __nv_bfloat16* xsL = (__nv_bfloat16*)(sm + XS_L);
    __nv_bfloat16* wsH = (__nv_bfloat16*)(sm + WS_H);
    __nv_bfloat16* wsL = (__nv_bfloat16*)(sm + WS_L);
    int tid = threadIdx.x, warp = tid >> 5;

    for (int i = tid; i < 256 * 16; i += 256) {
        int r = i >> 4, ch = i & 15;
        ((uint4*)(wsH + r * LDP))[ch] = ((const uint4*)(Whi + r * 128))[ch];
        ((uint4*)(wsL + r * LDP))[ch] = ((const uint4*)(Wlo + r * 128))[ch];
    }

    int ntiles = (N + 127) >> 7;

    for (int tile = blockIdx.x; tile < ntiles; tile += gridDim.x) {
        int row0 = tile << 7;
        __syncthreads();
        for (int ch = tid; ch < 2048; ch += 256) {
            int r  = ch >> 4;
            int c0 = (ch & 15) << 3;
            float v[8];
            int gr = row0 + r;
            if (gr < N) {
                float4 a = *(const float4*)(x + (size_t)gr * 128 + c0);
                float4 b = *(const float4*)(x + (size_t)gr * 128 + c0 + 4);
                v[0]=a.x; v[1]=a.y; v[2]=a.z; v[3]=a.w; v[4]=b.x; v[5]=b.y; v[6]=b.z; v[7]=b.w;
            } else {
                #pragma unroll
                for (int j = 0; j < 8; j++) v[j] = 0.f;
            }
            union { unsigned short u[8]; uint4 q; } H, L;
            #pragma unroll
            for (int j = 0; j < 8; j++) {
                __nv_bfloat16 hv = __float2bfloat16(v[j]);
                __nv_bfloat16 lv = __float2bfloat16(v[j] - __bfloat162float(hv));
                H.u[j] = __bfloat16_as_ushort(hv);
                L.u[j] = __bfloat16_as_ushort(lv);
            }
            *(uint4*)(xsH + r * LDP + c0) = H.q;
            *(uint4*)(xsL + r * LDP + c0) = L.q;
        }
        __syncthreads();

        #pragma unroll
        for (int nc = 0; nc < 4; nc++) {
            wmma::fragment<wmma::accumulator, 16, 16, 16, float> acc[4];
            #pragma unroll
            for (int f = 0; f < 4; f++) wmma::fill_fragment(acc[f], 0.0f);

            #pragma unroll
            for (int pass = 0; pass < 3; pass++) {
                const __nv_bfloat16* A = (pass == 2) ? xsL : xsH;
                const __nv_bfloat16* B = (pass == 1) ? wsL : wsH;
                #pragma unroll
                for (int k = 0; k < 8; k++) {
                    wmma::fragment<wmma::matrix_a, 16, 16, 16, __nv_bfloat16, wmma::row_major> af;
                    wmma::load_matrix_sync(af, A + (warp * 16) * LDP + k * 16, LDP);
                    #pragma unroll
                    for (int f = 0; f < 4; f++) {
                        wmma::fragment<wmma::matrix_b, 16, 16, 16, __nv_bfloat16, wmma::col_major> bf;
                        wmma::load_matrix_sync(bf, B + (nc * 64 + f * 16) * LDP + k * 16, LDP);
                        wmma::mma_sync(acc[f], af, bf, acc[f]);
                    }
                }
            }
            int gr0 = row0 + warp * 16;   // always < NMAX (padded buffers)
            #pragma unroll
            for (int f = 0; f < 4; f++) {
                int n0 = nc * 64 + f * 16;
                float* dst = (n0 < 128) ? (outm + (size_t)gr0 * 128 + n0)
                                        : (outu + (size_t)gr0 * 128 + (n0 - 128));
                wmma::store_matrix_sync(dst, acc[f], 128, wmma::mem_row_major);
            }
        }
    }
}

// ================= fused CSR aggregate + bias + tanh =================
__global__ __launch_bounds__(256) void agg_tanh(
    const float* __restrict__ m, const float* __restrict__ u,
    const float* __restrict__ bu, float* __restrict__ h, int N)
{
    int node = (blockIdx.x * blockDim.x + threadIdx.x) >> 5;
    int lane = threadIdx.x & 31;
    if (node >= N) return;
    int b = g_off[node], e = g_off[node + 1];

    float4 bb = *(const float4*)(bu + lane*4);
    float4 uu = *(const float4*)(u + (size_t)node*128 + lane*4);
    float4 acc = make_float4(uu.x + bb.x, uu.y + bb.y, uu.z + bb.z, uu.w + bb.w);

    int i = b;
    for (; i + 4 <= e; i += 4) {
        int   s0 = g_src_sorted[i],   s1 = g_src_sorted[i+1];
        int   s2 = g_src_sorted[i+2], s3 = g_src_sorted[i+3];
        float w0 = g_w_sorted[i],     w1 = g_w_sorted[i+1];
        float w2 = g_w_sorted[i+2],   w3 = g_w_sorted[i+3];
        float4 v0 = *(const float4*)(m + (size_t)s0*128 + lane*4);
        float4 v1 = *(const float4*)(m + (size_t)s1*128 + lane*4);
        float4 v2 = *(const float4*)(m + (size_t)s2*128 + lane*4);
        float4 v3 = *(const float4*)(m + (size_t)s3*128 + lane*4);
        acc.x = fmaf(w0, v0.x, fmaf(w1, v1.x, fmaf(w2, v2.x, fmaf(w3, v3.x, acc.x))));
        acc.y = fmaf(w0, v0.y, fmaf(w1, v1.y, fmaf(w2, v2.y, fmaf(w3, v3.y, acc.y))));
        acc.z = fmaf(w0, v0.z, fmaf(w1, v1.z, fmaf(w2, v2.z, fmaf(w3, v3.z, acc.z))));
        acc.w = fmaf(w0, v0.w, fmaf(w1, v1.w, fmaf(w2, v2.w, fmaf(w3, v3.w, acc.w))));
    }
    for (; i < e; i++) {
        int   s = g_src_sorted[i];
        float w = g_w_sorted[i];
        float4 v = *(const float4*)(m + (size_t)s*128 + lane*4);
        acc.x = fmaf(w, v.x, acc.x);
        acc.y = fmaf(w, v.y, acc.y);
        acc.z = fmaf(w, v.z, acc.z);
        acc.w = fmaf(w, v.w, acc.w);
    }
    acc.x = tanhf(acc.x); acc.y = tanhf(acc.y);
    acc.z = tanhf(acc.z); acc.w = tanhf(acc.w);
    *(float4*)(h + (size_t)node*128 + lane*4) = acc;
}

// ================= WMMA output GEMM: out = h @ Wout.T + bout (C=32) =================
#define OLDP 136
#define OA_H 0
#define OA_L (128*OLDP*2)
#define OW_H (2*128*OLDP*2)
#define OW_L (OW_H + 32*OLDP*2)
#define OBIAS (OW_L + 32*OLDP*2)
#define OUT_SMEM (OBIAS + 16*40*4)

__global__ __launch_bounds__(256, 1) void out_gemm_wmma(
    const float* __restrict__ h, const float* __restrict__ Wout,
    const float* __restrict__ bout, float* __restrict__ out,
    float* __restrict__ scratch, int N)
{
    extern __shared__ char sm[];
    __nv_bfloat16* aH = (__nv_bfloat16*)(sm + OA_H);
    __nv_bfloat16* aL = (__nv_bfloat16*)(sm + OA_L);
    __nv_bfloat16* wH = (__nv_bfloat16*)(sm + OW_H);
    __nv_bfloat16* wL = (__nv_bfloat16*)(sm + OW_L);
    float* bs = (float*)(sm + OBIAS);
    int tid = threadIdx.x, warp = tid >> 5, lane = tid & 31;

    // stage Wout 32x128 -> hi/lo
    for (int i = tid; i < 32 * 16; i += 256) {
        int r = i >> 4, ch = i & 15;
        float4 a = *(const float4*)(Wout + r * 128 + ch * 8);
        float4 b = *(const float4*)(Wout + r * 128 + ch * 8 + 4);
        float v[8] = {a.x, a.y, a.z, a.w, b.x, b.y, b.z, b.w};
        union { unsigned short u[8]; uint4 q; } H, L;
        #pragma unroll
        for (int j = 0; j < 8; j++) {
            __nv_bfloat16 hv = __float2bfloat16(v[j]);
            __nv_bfloat16 lv = __float2bfloat16(v[j] - __bfloat162float(hv));
            H.u[j] = __bfloat16_as_ushort(hv);
            L.u[j] = __bfloat16_as_ushort(lv);
        }
        *(uint4*)(wH + r * OLDP + ch * 8) = H.q;
        *(uint4*)(wL + r * OLDP + ch * 8) = L.q;
    }
    // bias tile [16][40], rows identical
    for (int i = tid; i < 16 * 40; i += 256) {
        int c = i % 40;
        bs[i] = (c < 32) ? bout[c] : 0.f;
    }

    int ntiles = (N + 127) >> 7;
    for (int tile = blockIdx.x; tile < ntiles; tile += gridDim.x) {
        int row0 = tile << 7;
        __syncthreads();
        for (int ch = tid; ch < 2048; ch += 256) {
            int r  = ch >> 4;
            int c0 = (ch & 15) << 3;
            float v[8];
            int gr = row0 + r;
            if (gr < N) {
                float4 a = *(const float4*)(h + (size_t)gr * 128 + c0);
                float4 b = *(const float4*)(h + (size_t)gr * 128 + c0 + 4);
                v[0]=a.x; v[1]=a.y; v[2]=a.z; v[3]=a.w; v[4]=b.x; v[5]=b.y; v[6]=b.z; v[7]=b.w;
            } else {
                #pragma unroll
                for (int j = 0; j < 8; j++) v[j] = 0.f;
            }
            union { unsigned short u[8]; uint4 q; } H, L;
            #pragma unroll
            for (int j = 0; j < 8; j++) {
                __nv_bfloat16 hv = __float2bfloat16(v[j]);
                __nv_bfloat16 lv = __float2bfloat16(v[j] - __bfloat162float(hv));
                H.u[j] = __bfloat16_as_ushort(hv);
                L.u[j] = __bfloat16_as_ushort(lv);
            }
            *(uint4*)(aH + r * OLDP + c0) = H.q;
            *(uint4*)(aL + r * OLDP + c0) = L.q;
        }
        __syncthreads();

        wmma::fragment<wmma::accumulator, 16, 16, 16, float> acc[2];
        #pragma unroll
        for (int f = 0; f < 2; f++)
            wmma::load_matrix_sync(acc[f], bs + f * 16, 40, wmma::mem_row_major);

        #pragma unroll
        for (int pass = 0; pass < 3; pass++) {
            const __nv_bfloat16* A = (pass == 2) ? aL : aH;
            const __nv_bfloat16* B = (pass == 1) ? wL : wH;
            #pragma unroll
            for (int k = 0; k < 8; k++) {
                wmma::fragment<wmma::matrix_a, 16, 16, 16, __nv_bfloat16, wmma::row_major> af;
                wmma::load_matrix_sync(af, A + (warp * 16) * OLDP + k * 16, OLDP);
                #pragma unroll
                for (int f = 0; f < 2; f++) {
                    wmma::fragment<wmma::matrix_b, 16, 16, 16, __nv_bfloat16, wmma::col_major> bf;
                    wmma::load_matrix_sync(bf, B + (f * 16) * OLDP + k * 16, OLDP);
                    wmma::mma_sync(acc[f], af, bf, acc[f]);
                }
            }
        }
        int gr0 = row0 + warp * 16;
        if (gr0 + 16 <= N) {
            wmma::store_matrix_sync(out + (size_t)gr0 * 32,      acc[0], 32, wmma::mem_row_major);
            wmma::store_matrix_sync(out + (size_t)gr0 * 32 + 16, acc[1], 32, wmma::mem_row_major);
        } else if (gr0 < N) {
            // partial strip: stage via global scratch, copy valid rows
            float* sc = scratch + (size_t)gr0 * 32;
            wmma::store_matrix_sync(sc,      acc[0], 32, wmma::mem_row_major);
            wmma::store_matrix_sync(sc + 16, acc[1], 32, wmma::mem_row_major);
            __syncwarp();
            for (int r = 0; r < 16; r++) {
                int gr = gr0 + r;
                if (gr < N) out[(size_t)gr * 32 + lane] = sc[r * 32 + lane];
            }
        }
    }
}

extern "C" void kernel_launch(void* const* d_in, const int* in_sizes, int n_in,
                              void* d_out, int out_size) {
    const float* x    = (const float*)d_in[0];
    const void*  ei   = d_in[1];
    const float* ew   = (const float*)d_in[2];
    const float* Wm0  = (const float*)d_in[3];
    const float* Wu0  = (const float*)d_in[4];
    const float* bu0  = (const float*)d_in[5];
    const float* Wm1  = (const float*)d_in[6];
    const float* Wu1  = (const float*)d_in[7];
    const float* bu1  = (const float*)d_in[8];
    const float* Wm2  = (const float*)d_in[9];
    const float* Wu2  = (const float*)d_in[10];
    const float* bu2  = (const float*)d_in[11];
    const float* Wout = (const float*)d_in[12];
    const float* bout = (const float*)d_in[13];
    float* out = (float*)d_out;

    int N = in_sizes[0] / 128;
    int E = in_sizes[2];

    __nv_bfloat16* pW;
    float *pm, *pu, *ph;
    cudaGetSymbolAddress((void**)&pW, g_Wbf);
    cudaGetSymbolAddress((void**)&pm, g_m);
    cudaGetSymbolAddress((void**)&pu, g_u);
    cudaGetSymbolAddress((void**)&ph, g_h);

    static cudaStream_t s2 = nullptr;
    static cudaEvent_t evF = nullptr, evC = nullptr;
    if (!s2) {
        cudaStreamCreateWithFlags(&s2, cudaStreamNonBlocking);
        cudaEventCreateWithFlags(&evF, cudaEventDisableTiming);
        cudaEventCreateWithFlags(&evC, cudaEventDisableTiming);
    }

    static bool attrs_set = false;
    if (!attrs_set) {
        cudaFuncSetAttribute(dual_gemm_wmma, cudaFuncAttributeMaxDynamicSharedMemorySize, GEMM_SMEM);
        cudaFuncSetAttribute(out_gemm_wmma,  cudaFuncAttributeMaxDynamicSharedMemorySize, OUT_SMEM);
        attrs_set = true;
    }

    // fork: CSR build on s2, weights prep + gemm0 on main
    cudaEventRecord(evF, 0);
    cudaStreamWaitEvent(s2, evF, 0);
    int eb = (E + 255) / 256;
    zero_kernel<<<148, 256, 0, s2>>>(ei, N);
    hist_kernel<<<eb, 256, 0, s2>>>(ei, E);
    scan_kernel<<<1, 1024, 0, s2>>>(N);
    scatter_kernel<<<eb, 256, 0, s2>>>(ei, ew, E);
    cudaEventRecord(evC, s2);

    prep_kernel<<<148, 256>>>(Wm0, Wu0, Wm1, Wu1, Wm2, Wu2);

    int ab = (N * 32 + 255) / 256;

    const float* cur = x;
    for (int l = 0; l < 3; l++) {
        const float* bu = (l == 0) ? bu0 : (l == 1) ? bu1 : bu2;
        const __nv_bfloat16* Whi = pW + (size_t)l * 2 * 256 * 128;
        const __nv_bfloat16* Wlo = Whi + 256 * 128;
        dual_gemm_wmma<<<148, 256, GEMM_SMEM>>>(cur, Whi, Wlo, pm, pu, N);
        if (l == 0) cudaStreamWaitEvent(0, evC, 0);   // join CSR before first aggregate
        float* hbuf = ph + (size_t)(l & 1) * NMAX * 128;
        agg_tanh<<<ab, 256>>>(pm, pu, bu, hbuf, N);
        cur = hbuf;
    }
    out_gemm_wmma<<<148, 256, OUT_SMEM>>>(cur, Wout, bout, out, pu, N);
    (void)n_in; (void)out_size;
}